// round 1
// baseline (speedup 1.0000x reference)
#include <cuda_runtime.h>
#include <cstddef>

// Problem dims (fixed by reference)
#define BATCH 8192
#define INF   784
#define HID   4096
#define OUTD  10

// Scratch for the hidden activation h = clip(x @ sign(W1)^T + b1)
// 8192*4096 floats = 128 MB. Device global (no runtime allocation).
__device__ float g_h[(size_t)BATCH * HID];

// ---------------------------------------------------------------------------
// Kernel 1: h = clip(x @ sign(W1)^T + b1, -1, 1)
//   X  : [BATCH, INF]  row-major (K contiguous)
//   W1 : [HID,   INF]  row-major (K contiguous)  -> NT gemm, C[m,n]=sum_k A[m,k]*B[n,k]
// Tiling: BM=128, BN=128, BK=16, 256 threads, 8x8 per-thread microtile.
// INF = 784 = 49*16 exactly -> no K remainder. M,N divisible by 128.
// ---------------------------------------------------------------------------
#define BM 128
#define BN 128
#define BK 16
#define SPAD 4   // smem row padding (floats); keeps 16B alignment (132*4=528, 528%16==0)

__global__ __launch_bounds__(256, 2)
void fc1_kernel(const float* __restrict__ X,
                const float* __restrict__ W1,
                const float* __restrict__ b1)
{
    __shared__ float As[BK][BM + SPAD];
    __shared__ float Bs[BK][BN + SPAD];

    const int tid = threadIdx.x;
    const int tx  = tid & 15;        // 0..15  -> N direction
    const int ty  = tid >> 4;        // 0..15  -> M direction
    const int bm  = blockIdx.y * BM;
    const int bn  = blockIdx.x * BN;

    float acc[8][8];
    #pragma unroll
    for (int i = 0; i < 8; i++)
        #pragma unroll
        for (int j = 0; j < 8; j++)
            acc[i][j] = 0.f;

    for (int k0 = 0; k0 < INF; k0 += BK) {
        // --- load A tile: 128 rows x 16 k = 512 float4, 2 per thread ---
        #pragma unroll
        for (int r = 0; r < 2; r++) {
            const int f   = tid + 256 * r;
            const int row = f >> 2;          // 4 float4 per row
            const int kc  = (f & 3) * 4;
            const float4 v = *(const float4*)&X[(size_t)(bm + row) * INF + k0 + kc];
            As[kc + 0][row] = v.x;
            As[kc + 1][row] = v.y;
            As[kc + 2][row] = v.z;
            As[kc + 3][row] = v.w;
        }
        // --- load B tile with sign() applied ---
        #pragma unroll
        for (int r = 0; r < 2; r++) {
            const int f   = tid + 256 * r;
            const int row = f >> 2;
            const int kc  = (f & 3) * 4;
            const float4 v = *(const float4*)&W1[(size_t)(bn + row) * INF + k0 + kc];
            Bs[kc + 0][row] = (v.x > 0.f) ? 1.f : ((v.x < 0.f) ? -1.f : 0.f);
            Bs[kc + 1][row] = (v.y > 0.f) ? 1.f : ((v.y < 0.f) ? -1.f : 0.f);
            Bs[kc + 2][row] = (v.z > 0.f) ? 1.f : ((v.z < 0.f) ? -1.f : 0.f);
            Bs[kc + 3][row] = (v.w > 0.f) ? 1.f : ((v.w < 0.f) ? -1.f : 0.f);
        }
        __syncthreads();

        #pragma unroll
        for (int kk = 0; kk < BK; kk++) {
            float a[8], b[8];
            *(float4*)&a[0] = *(const float4*)&As[kk][ty * 8];
            *(float4*)&a[4] = *(const float4*)&As[kk][ty * 8 + 4];
            *(float4*)&b[0] = *(const float4*)&Bs[kk][tx * 8];
            *(float4*)&b[4] = *(const float4*)&Bs[kk][tx * 8 + 4];
            #pragma unroll
            for (int i = 0; i < 8; i++)
                #pragma unroll
                for (int j = 0; j < 8; j++)
                    acc[i][j] += a[i] * b[j];
        }
        __syncthreads();
    }

    // --- epilogue: + b1, hardtanh, store to g_h ---
    float bias[8];
    #pragma unroll
    for (int j = 0; j < 8; j++)
        bias[j] = b1[bn + tx * 8 + j];

    #pragma unroll
    for (int i = 0; i < 8; i++) {
        const int m = bm + ty * 8 + i;
        float v[8];
        #pragma unroll
        for (int j = 0; j < 8; j++) {
            float t = acc[i][j] + bias[j];
            v[j] = fminf(fmaxf(t, -1.f), 1.f);
        }
        float* dst = &g_h[(size_t)m * HID + bn + tx * 8];
        *(float4*)&dst[0] = make_float4(v[0], v[1], v[2], v[3]);
        *(float4*)&dst[4] = make_float4(v[4], v[5], v[6], v[7]);
    }
}

// ---------------------------------------------------------------------------
// Kernel 2: out = h @ W2^T + b2   (M=8192, N=10, K=4096; bandwidth-bound on h)
// 8 warps/block, one warp per row. W2 staged in smem in 10x1024 chunks (40KB).
// ---------------------------------------------------------------------------
#define K2CHUNK 1024

__global__ __launch_bounds__(256)
void fc2_kernel(const float* __restrict__ W2,
                const float* __restrict__ b2,
                float* __restrict__ out)
{
    __shared__ float W2s[OUTD][K2CHUNK];

    const int tid  = threadIdx.x;
    const int warp = tid >> 5;
    const int lane = tid & 31;
    const int row  = blockIdx.x * 8 + warp;

    float acc[OUTD];
    #pragma unroll
    for (int o = 0; o < OUTD; o++) acc[o] = 0.f;

    for (int kt = 0; kt < HID; kt += K2CHUNK) {
        // cooperative load of W2 chunk: 10*1024 floats = 2560 float4
        for (int f = tid; f < OUTD * (K2CHUNK / 4); f += 256) {
            const int o = f / (K2CHUNK / 4);
            const int c = f % (K2CHUNK / 4);
            *(float4*)&W2s[o][c * 4] =
                *(const float4*)&W2[(size_t)o * HID + kt + c * 4];
        }
        __syncthreads();

        const float* hrow = &g_h[(size_t)row * HID + kt];
        #pragma unroll
        for (int i = 0; i < K2CHUNK / 128; i++) {       // 8 iters
            const int j = (i * 32 + lane) * 4;
            const float4 h4 = *(const float4*)&hrow[j];
            #pragma unroll
            for (int o = 0; o < OUTD; o++) {
                const float4 w4 = *(const float4*)&W2s[o][j];
                acc[o] += h4.x * w4.x + h4.y * w4.y + h4.z * w4.z + h4.w * w4.w;
            }
        }
        __syncthreads();
    }

    // warp butterfly reduction: every lane ends with the full sums
    #pragma unroll
    for (int o = 0; o < OUTD; o++) {
        #pragma unroll
        for (int s = 16; s > 0; s >>= 1)
            acc[o] += __shfl_xor_sync(0xffffffffu, acc[o], s);
    }

    if (lane == 0) {
        #pragma unroll
        for (int o = 0; o < OUTD; o++)
            out[(size_t)row * OUTD + o] = acc[o] + b2[o];
    }
}

// ---------------------------------------------------------------------------
// Launch (graph-capturable: kernel launches only)
// Inputs (metadata order): x[8192*784], W1[4096*784], b1[4096], W2[10*4096], b2[10]
// Output: float [8192*10]
// ---------------------------------------------------------------------------
extern "C" void kernel_launch(void* const* d_in, const int* in_sizes, int n_in,
                              void* d_out, int out_size)
{
    const float* X  = (const float*)d_in[0];
    const float* W1 = (const float*)d_in[1];
    const float* b1 = (const float*)d_in[2];
    const float* W2 = (const float*)d_in[3];
    const float* b2 = (const float*)d_in[4];
    float* out = (float*)d_out;

    dim3 grid1(HID / BN, BATCH / BM);   // 32 x 64
    fc1_kernel<<<grid1, 256>>>(X, W1, b1);

    fc2_kernel<<<BATCH / 8, 256>>>(W2, b2, out);
}

// round 4
// speedup vs baseline: 4.2883x; 4.2883x over previous
#include <cuda_runtime.h>
#include <cuda_bf16.h>
#include <cstdint>
#include <cstddef>

// ---------------------------------------------------------------------------
// Problem dims
// ---------------------------------------------------------------------------
#define BATCH 8192
#define INF   784
#define KPAD  832          // 13 * 64, zero-padded K
#define HID   4096
#define OUTD  10

#define BM 128
#define BN 128
#define BK 64              // bf16 chunk: 128 bytes per row
#define NCHUNK (KPAD / BK) // 13
#define NBLK   (HID / BN)  // 32 n-tiles
#define NSLAB  (NBLK * 2)  // 64 partial slabs (one per warp-column-half)

// ---------------------------------------------------------------------------
// Device scratch (static -> no allocations)
// ---------------------------------------------------------------------------
__device__ __nv_bfloat16 g_xhi[(size_t)BATCH * KPAD];
__device__ __nv_bfloat16 g_xlo[(size_t)BATCH * KPAD];
__device__ __nv_bfloat16 g_wb [(size_t)HID   * KPAD];
__device__ float g_part[(size_t)NSLAB * BATCH * OUTD];   // 21 MB

// ---------------------------------------------------------------------------
// PTX helpers (sm_80-class; valid at compute_100)
// ---------------------------------------------------------------------------
__device__ __forceinline__ uint32_t smem_u32(const void* p) {
    uint32_t a;
    asm("{ .reg .u64 t; cvta.to.shared.u64 t, %1; cvt.u32.u64 %0, t; }"
        : "=r"(a) : "l"(p));
    return a;
}

__device__ __forceinline__ void cp16(uint32_t saddr, const void* gaddr) {
    asm volatile("cp.async.cg.shared.global [%0], [%1], 16;"
                 :: "r"(saddr), "l"(gaddr) : "memory");
}
__device__ __forceinline__ void cp_commit() {
    asm volatile("cp.async.commit_group;" ::: "memory");
}
__device__ __forceinline__ void cp_wait1() {
    asm volatile("cp.async.wait_group 1;" ::: "memory");
}
__device__ __forceinline__ void cp_wait0() {
    asm volatile("cp.async.wait_group 0;" ::: "memory");
}

__device__ __forceinline__ void ldsm4(uint32_t& r0, uint32_t& r1,
                                      uint32_t& r2, uint32_t& r3, uint32_t a) {
    asm volatile("ldmatrix.sync.aligned.m8n8.x4.shared.b16 {%0,%1,%2,%3}, [%4];"
                 : "=r"(r0), "=r"(r1), "=r"(r2), "=r"(r3) : "r"(a));
}

__device__ __forceinline__ void mma16816(float* c, const uint32_t* a, const uint32_t* b) {
    asm volatile(
        "mma.sync.aligned.m16n8k16.row.col.f32.bf16.bf16.f32 "
        "{%0,%1,%2,%3}, {%4,%5,%6,%7}, {%8,%9}, {%0,%1,%2,%3};"
        : "+f"(c[0]), "+f"(c[1]), "+f"(c[2]), "+f"(c[3])
        : "r"(a[0]), "r"(a[1]), "r"(a[2]), "r"(a[3]), "r"(b[0]), "r"(b[1]));
}

// ---------------------------------------------------------------------------
// Dynamic SMEM layout
//   [0,512)        b1 slice (128 f32)
//   [512,6656)     W2^T slice: 128 cols x 12 f32 (10 used, padded)
//   [8192,...)     2 stages x { Ahi 16K | Alo 16K | B 16K }
// ---------------------------------------------------------------------------
#define SM_B1      0
#define SM_W2V     512
#define SM_STAGE0  8192
#define STAGE_SZ   49152
#define OFF_ALO    16384
#define OFF_B      32768
#define SMEM_TOTAL (SM_STAGE0 + 2 * STAGE_SZ)   // 106496 B -> 2 CTAs/SM

// ---------------------------------------------------------------------------
// prep kernels
// ---------------------------------------------------------------------------
__global__ __launch_bounds__(256) void prep_x(const float* __restrict__ X) {
    int idx = blockIdx.x * 256 + threadIdx.x;
    int m   = idx / (KPAD / 4);
    int k4  = (idx - m * (KPAD / 4)) * 4;
    if (m >= BATCH) return;
    __nv_bfloat16 hi[4], lo[4];
    if (k4 < INF) {
        const float4 v = *(const float4*)&X[(size_t)m * INF + k4];
        const float vv[4] = {v.x, v.y, v.z, v.w};
        #pragma unroll
        for (int e = 0; e < 4; e++) {
            hi[e] = __float2bfloat16(vv[e]);
            lo[e] = __float2bfloat16(vv[e] - __bfloat162float(hi[e]));
        }
    } else {
        #pragma unroll
        for (int e = 0; e < 4; e++) { hi[e] = __float2bfloat16(0.f); lo[e] = hi[e]; }
    }
    *(uint2*)&g_xhi[(size_t)m * KPAD + k4] = *(uint2*)hi;
    *(uint2*)&g_xlo[(size_t)m * KPAD + k4] = *(uint2*)lo;
}

__global__ __launch_bounds__(256) void prep_w(const float* __restrict__ W1) {
    int idx = blockIdx.x * 256 + threadIdx.x;
    int n   = idx / (KPAD / 4);
    int k4  = (idx - n * (KPAD / 4)) * 4;
    if (n >= HID) return;
    __nv_bfloat16 s[4];
    if (k4 < INF) {
        const float4 v = *(const float4*)&W1[(size_t)n * INF + k4];
        const float vv[4] = {v.x, v.y, v.z, v.w};
        #pragma unroll
        for (int e = 0; e < 4; e++) {
            float sv = (vv[e] > 0.f) ? 1.f : ((vv[e] < 0.f) ? -1.f : 0.f);
            s[e] = __float2bfloat16(sv);
        }
    } else {
        #pragma unroll
        for (int e = 0; e < 4; e++) s[e] = __float2bfloat16(0.f);
    }
    *(uint2*)&g_wb[(size_t)n * KPAD + k4] = *(uint2*)s;
}

// ---------------------------------------------------------------------------
// fc1 (bf16 hi/lo tensor-core GEMM) + fused fc2 partial
// ---------------------------------------------------------------------------
__global__ __launch_bounds__(256, 2) void fc1_mma(const float* __restrict__ b1,
                                                  const float* __restrict__ W2)
{
    extern __shared__ char smem[];
    const uint32_t sb = smem_u32(smem);
    const int tid  = threadIdx.x;
    const int warp = tid >> 5;
    const int lane = tid & 31;
    const int wm   = warp >> 1;      // 0..3 -> m offset 32*wm
    const int wn   = warp & 1;       // 0..1 -> n offset 64*wn
    const int bn   = blockIdx.x * BN;
    const int bm   = blockIdx.y * BM;

    const char* xh = (const char*)g_xhi + (size_t)bm * (KPAD * 2);
    const char* xl = (const char*)g_xlo + (size_t)bm * (KPAD * 2);
    const char* wb = (const char*)g_wb  + (size_t)bn * (KPAD * 2);

    // per-thread cp.async mapping: 4 units of 16B per region per chunk
    const int ldrow = tid >> 3;             // base row (0..31), step 32
    const int ldub  = (tid & 7) * 16;       // byte within 128B row

    // ---- prologue: issue chunk 0, then stage b1/W2 ----
    {
        #pragma unroll
        for (int r = 0; r < 4; r++) {
            const int row  = ldrow + 32 * r;
            const uint32_t so = (uint32_t)(row * 128 + (ldub ^ ((row & 7) << 4)));
            const size_t  go = (size_t)row * (KPAD * 2) + ldub;
            cp16(sb + SM_STAGE0 + so,           xh + go);
            cp16(sb + SM_STAGE0 + OFF_ALO + so, xl + go);
            cp16(sb + SM_STAGE0 + OFF_B + so,   wb + go);
        }
        cp_commit();
    }
    {
        float* b1s = (float*)(smem + SM_B1);
        float* w2v = (float*)(smem + SM_W2V);
        for (int i = tid; i < BN; i += 256) b1s[i] = b1[bn + i];
        for (int i = tid; i < BN * 12; i += 256) {
            int col = i / 12, o = i - col * 12;
            w2v[i] = (o < OUTD) ? W2[(size_t)o * HID + bn + col] : 0.f;
        }
    }

    // ldmatrix per-lane address components
    const int xl4   = (lane & 7) << 4;                       // swizzle XOR term
    const int arow  = (lane & 7) + 8 * ((lane >> 3) & 1);    // A: 16 rows
    const int akb   = (lane >> 4) * 16;
    const int brow  = (lane & 7) + 8 * (lane >> 4);          // B: 16 rows
    const int bkb   = ((lane >> 3) & 1) * 16;

    float acc[2][8][4];
    #pragma unroll
    for (int mi = 0; mi < 2; mi++)
        #pragma unroll
        for (int ni = 0; ni < 8; ni++)
            #pragma unroll
            for (int j = 0; j < 4; j++) acc[mi][ni][j] = 0.f;

    for (int c = 0; c < NCHUNK; c++) {
        if (c + 1 < NCHUNK) {
            const uint32_t sbase = sb + SM_STAGE0 + ((c + 1) & 1) * STAGE_SZ;
            const size_t   kb   = (size_t)(c + 1) * 128;
            #pragma unroll
            for (int r = 0; r < 4; r++) {
                const int row  = ldrow + 32 * r;
                const uint32_t so = (uint32_t)(row * 128 + (ldub ^ ((row & 7) << 4)));
                const size_t  go = (size_t)row * (KPAD * 2) + kb + ldub;
                cp16(sbase + so,           xh + go);
                cp16(sbase + OFF_ALO + so, xl + go);
                cp16(sbase + OFF_B + so,   wb + go);
            }
            cp_commit();
            cp_wait1();
        } else {
            cp_wait0();
        }
        __syncthreads();

        const uint32_t sA  = sb + SM_STAGE0 + (c & 1) * STAGE_SZ;
        const uint32_t sAl = sA + OFF_ALO;
        const uint32_t sB  = sA + OFF_B;

        #pragma unroll
        for (int ks = 0; ks < 4; ks++) {
            const int ko = ks * 32;
            uint32_t ah[2][4], al[2][4], bf[8][2];
            #pragma unroll
            for (int mi = 0; mi < 2; mi++) {
                const int row = wm * 32 + mi * 16 + arow;
                const uint32_t off = (uint32_t)(row * 128 + ((ko + akb) ^ xl4));
                ldsm4(ah[mi][0], ah[mi][1], ah[mi][2], ah[mi][3], sA + off);
                ldsm4(al[mi][0], al[mi][1], al[mi][2], al[mi][3], sAl + off);
            }
            #pragma unroll
            for (int nj = 0; nj < 4; nj++) {
                const int row = wn * 64 + nj * 16 + brow;
                const uint32_t off = (uint32_t)(row * 128 + ((ko + bkb) ^ xl4));
                ldsm4(bf[2 * nj][0], bf[2 * nj][1], bf[2 * nj + 1][0], bf[2 * nj + 1][1],
                      sB + off);
            }
            #pragma unroll
            for (int mi = 0; mi < 2; mi++)
                #pragma unroll
                for (int ni = 0; ni < 8; ni++) {
                    mma16816(acc[mi][ni], ah[mi], bf[ni]);
                    mma16816(acc[mi][ni], al[mi], bf[ni]);
                }
        }
        __syncthreads();
    }

    // ---- epilogue: +b1, hardtanh, fused fc2 partial ----
    const float* b1s = (const float*)(smem + SM_B1);
    const float4* w2v4 = (const float4*)(smem + SM_W2V);

    float acco[2][2][OUTD];
    #pragma unroll
    for (int mi = 0; mi < 2; mi++)
        #pragma unroll
        for (int jh = 0; jh < 2; jh++)
            #pragma unroll
            for (int o = 0; o < OUTD; o++) acco[mi][jh][o] = 0.f;

    #pragma unroll
    for (int ni = 0; ni < 8; ni++) {
        #pragma unroll
        for (int jl = 0; jl < 2; jl++) {
            const int ncol = wn * 64 + ni * 8 + 2 * (lane & 3) + jl;
            const float bias = b1s[ncol];
            const float4 w0 = w2v4[ncol * 3 + 0];
            const float4 w1 = w2v4[ncol * 3 + 1];
            const float4 w2_ = w2v4[ncol * 3 + 2];
            #pragma unroll
            for (int mi = 0; mi < 2; mi++) {
                #pragma unroll
                for (int jh = 0; jh < 2; jh++) {
                    float hv = acc[mi][ni][jh * 2 + jl] + bias;
                    hv = fminf(fmaxf(hv, -1.f), 1.f);
                    acco[mi][jh][0] += hv * w0.x;  acco[mi][jh][1] += hv * w0.y;
                    acco[mi][jh][2] += hv * w0.z;  acco[mi][jh][3] += hv * w0.w;
                    acco[mi][jh][4] += hv * w1.x;  acco[mi][jh][5] += hv * w1.y;
                    acco[mi][jh][6] += hv * w1.z;  acco[mi][jh][7] += hv * w1.w;
                    acco[mi][jh][8] += hv * w2_.x; acco[mi][jh][9] += hv * w2_.y;
                }
            }
        }
    }

    // reduce across the 4 lanes of each quad (they cover distinct n cols)
    #pragma unroll
    for (int mi = 0; mi < 2; mi++)
        #pragma unroll
        for (int jh = 0; jh < 2; jh++)
            #pragma unroll
            for (int o = 0; o < OUTD; o++) {
                float v = acco[mi][jh][o];
                v += __shfl_xor_sync(0xffffffffu, v, 1);
                v += __shfl_xor_sync(0xffffffffu, v, 2);
                acco[mi][jh][o] = v;
            }

    // FIX (R4): slab per (n-tile, warp-column-half) -> no cross-warp overwrite
    if ((lane & 3) == 0) {
        const size_t slab = (size_t)(blockIdx.x * 2 + wn);
        #pragma unroll
        for (int mi = 0; mi < 2; mi++)
            #pragma unroll
            for (int jh = 0; jh < 2; jh++) {
                const int row = bm + wm * 32 + mi * 16 + (lane >> 2) + 8 * jh;
                float* dst = g_part + (slab * BATCH + row) * OUTD;
                #pragma unroll
                for (int o = 0; o < OUTD; o++) dst[o] = acco[mi][jh][o];
            }
    }
}

// ---------------------------------------------------------------------------
// reduce: out[m][o] = b2[o] + sum_p g_part[p][m][o]
// ---------------------------------------------------------------------------
__global__ __launch_bounds__(256) void reduce_out(const float* __restrict__ b2,
                                                  float* __restrict__ out)
{
    const int idx = blockIdx.x * 256 + threadIdx.x;
    if (idx >= BATCH * OUTD) return;
    const int o = idx % OUTD;
    float s = b2[o];
    #pragma unroll
    for (int p = 0; p < NSLAB; p++)
        s += g_part[(size_t)p * (BATCH * OUTD) + idx];
    out[idx] = s;
}

// ---------------------------------------------------------------------------
// Launch
// ---------------------------------------------------------------------------
extern "C" void kernel_launch(void* const* d_in, const int* in_sizes, int n_in,
                              void* d_out, int out_size)
{
    const float* X  = (const float*)d_in[0];
    const float* W1 = (const float*)d_in[1];
    const float* b1 = (const float*)d_in[2];
    const float* W2 = (const float*)d_in[3];
    const float* b2 = (const float*)d_in[4];
    float* out = (float*)d_out;

    cudaFuncSetAttribute(fc1_mma, cudaFuncAttributeMaxDynamicSharedMemorySize, SMEM_TOTAL);

    prep_x<<<(BATCH * (KPAD / 4)) / 256, 256>>>(X);
    prep_w<<<(HID   * (KPAD / 4)) / 256, 256>>>(W1);

    dim3 grid1(NBLK, BATCH / BM);   // 32 x 64
    fc1_mma<<<grid1, 256, SMEM_TOTAL>>>(b1, W2);

    reduce_out<<<(BATCH * OUTD + 255) / 256, 256>>>(b2, out);
}